// round 5
// baseline (speedup 1.0000x reference)
#include <cuda_runtime.h>
#include <cuda_bf16.h>
#include <cstdint>

// OHEM smooth-L1 loss. y_pred,y_true: [64, 262144] fp32 -> scalar fp32.
// Single fused kernel:
//   phase 1: sweep; stage "interesting" (p,t) pairs (pos OR |p|>=1.5625) into
//            private smem slots (1 FFMA + 1 FSETP + predicated STS per element).
//   phase 2: per-thread processing of staged entries -> pos stats + counts-only
//            2048-bin histogram (global RED, L2-resident) + big-neg a-sum.
//   row ticket: last block of each row computes the row's neg-loss sum from the
//            L2-hot histogram (linear reconstruction: sum_sel = suma - unsel - k/2).
//   global ticket: last row-finisher emits the final scalar.

static constexpr int B = 64;
static constexpr int N = 256 * 256 * 4;        // 262144
static constexpr int NBINS = 2048;
static constexpr unsigned CUT_BITS = 0x3FC80000u;   // 1.5625f
static constexpr float   CUTF = 1.5625f;

static constexpr int TPB = 256;
static constexpr int VEC = 4;
static constexpr int ITERS = 2;
static constexpr int EPB = TPB * VEC * ITERS;   // 2048
static constexpr int BPR = N / EPB;             // 128

struct Zeroed {
    unsigned hist[B][NBINS];   // big-neg counts, bin = (key-CUT)>>13 clamped
    unsigned pos_cnt[B];
    unsigned big_cnt[B];
    double   pos_sum[B];
    double   big_suma[B];
    unsigned row_ticket[B];
    double   ns, nc;
    unsigned ticket2;
};
__device__ Zeroed g_z;         // ~513 KB memset per launch

// valid in thread 0; internally barriered; all threads must call
__device__ double block_reduce_double(double v) {
    __shared__ double sh[32];
    int lane = threadIdx.x & 31, w = threadIdx.x >> 5;
    #pragma unroll
    for (int o = 16; o; o >>= 1) v += __shfl_down_sync(0xffffffffu, v, o);
    __syncthreads();
    if (lane == 0) sh[w] = v;
    __syncthreads();
    double r = 0.0;
    if (w == 0) {
        int nw = (blockDim.x + 31) >> 5;
        r = (lane < nw) ? sh[lane] : 0.0;
        #pragma unroll
        for (int o = 16; o; o >>= 1) r += __shfl_down_sync(0xffffffffu, r, o);
    }
    __syncthreads();
    return r;
}

__device__ __forceinline__ float fsl1(float a) {
    float u = fminf(a, 1.0f);
    return fmaf(u, fmaf(0.5f, u, -1.0f), a);   // exact smooth_l1, branch-free
}
__device__ __forceinline__ float bin_center(int b) {
    return __uint_as_float(CUT_BITS + ((unsigned)b << 13) + (1u << 12));
}

// warp-0 suffix select: find b*, c = count(bins > b*), c < keff <= c + h[b*]
__device__ void warp_select(const unsigned* h, int nbins, unsigned keff,
                            int* out_b, unsigned* out_c) {
    const int lane = threadIdx.x;
    const int chunk = nbins >> 5;
    unsigned cs = 0;
    for (int j = 0; j < chunk; j++) cs += h[lane * chunk + j];
    unsigned v = cs;
    #pragma unroll
    for (int off = 1; off < 32; off <<= 1) {
        unsigned g = __shfl_down_sync(0xffffffffu, v, off);
        if (lane + off < 32) v += g;
    }
    unsigned vnext = __shfl_down_sync(0xffffffffu, v, 1);
    if (lane == 31) vnext = 0u;
    bool hit = (v >= keff) && (vnext < keff);
    unsigned hb = __ballot_sync(0xffffffffu, hit);
    int c = __ffs(hb) - 1;
    unsigned S = __shfl_sync(0xffffffffu, vnext, c);
    for (int g = (chunk >> 5) - 1; g >= 0; g--) {
        unsigned hv = h[c * chunk + g * 32 + lane];
        unsigned w = hv;
        #pragma unroll
        for (int off = 1; off < 32; off <<= 1) {
            unsigned gg = __shfl_down_sync(0xffffffffu, w, off);
            if (lane + off < 32) w += gg;
        }
        unsigned wnext = __shfl_down_sync(0xffffffffu, w, 1);
        if (lane == 31) wnext = 0u;
        unsigned tot = __shfl_sync(0xffffffffu, w, 0);
        bool hit2 = (S + w >= keff) && (S + wnext < keff);
        unsigned hb2 = __ballot_sync(0xffffffffu, hit2);
        if (hb2) {
            int l = __ffs(hb2) - 1;
            unsigned wl = __shfl_sync(0xffffffffu, w, l);
            unsigned hl = __shfl_sync(0xffffffffu, hv, l);
            if (lane == 0) { *out_b = c * chunk + g * 32 + l; *out_c = S + wl - hl; }
            return;
        }
        S += tot;
    }
}

__global__ void __launch_bounds__(TPB) fused(const float* __restrict__ yp,
                                             const float* __restrict__ yt,
                                             float* __restrict__ out) {
    __shared__ float2 sbuf[TPB][9];             // 8 slots + pad; 18.4 KB (reused later)
    __shared__ int s_b; __shared__ unsigned s_c;
    __shared__ int s_fin, s_fin2;
    const int r = blockIdx.y;
    const int tid = threadIdx.x;
    const size_t base = (size_t)r * N + (size_t)blockIdx.x * EPB;
    int cnt = 0;

    // ---- phase 1: sweep + stage ----
    #pragma unroll
    for (int it = 0; it < ITERS; it++) {
        size_t idx = base + (size_t)it * (TPB * VEC) + (size_t)tid * VEC;
        float4 p = *reinterpret_cast<const float4*>(yp + idx);
        float4 t = *reinterpret_cast<const float4*>(yt + idx);
        float pv[4] = {p.x, p.y, p.z, p.w};
        float tv[4] = {t.x, t.y, t.z, t.w};
        #pragma unroll
        for (int j = 0; j < 4; j++) {
            // t!=0 -> w huge; t==0 -> w=|p|.  interesting <=> w >= CUTF
            float w = fmaf(fabsf(tv[j]), 1e38f, fabsf(pv[j]));
            if (w >= CUTF) { sbuf[tid][cnt] = make_float2(pv[j], tv[j]); cnt++; }
        }
    }

    // ---- phase 2: process staged entries ----
    float psum = 0.f, bsum = 0.f; int pc = 0, bc = 0;
    for (int c = 0; c < cnt; c++) {
        float2 e = sbuf[tid][c];
        if (e.y != 0.f) {                        // positive
            psum += fsl1(fabsf(e.x - e.y));
            pc++;
        } else {                                 // big negative (|p| >= 1.5625)
            float a = fabsf(e.x);
            unsigned bin = (__float_as_uint(a) - CUT_BITS) >> 13;
            if (bin > (unsigned)(NBINS - 1)) bin = NBINS - 1;
            atomicAdd(&g_z.hist[r][bin], 1u);
            bsum += a; bc++;
        }
    }

    double dps = block_reduce_double((double)psum);
    double dbs = block_reduce_double((double)bsum);
    double dpc = block_reduce_double((double)pc);
    double dbc = block_reduce_double((double)bc);
    if (tid == 0) {
        if (dpc != 0.0) { atomicAdd(&g_z.pos_sum[r], dps); atomicAdd(&g_z.pos_cnt[r], (unsigned)(dpc + 0.5)); }
        if (dbc != 0.0) { atomicAdd(&g_z.big_suma[r], dbs); atomicAdd(&g_z.big_cnt[r], (unsigned)(dbc + 0.5)); }
        __threadfence();
        s_fin = (atomicAdd(&g_z.row_ticket[r], 1u) == (unsigned)(BPR - 1)) ? 1 : 0;
    }
    __syncthreads();
    if (!s_fin) return;

    // ================= row finish (last block of row r; hist is L2-hot) =====
    __threadfence();
    unsigned* s_h = reinterpret_cast<unsigned*>(&sbuf[0][0]);
    float*    s_f = reinterpret_cast<float*>(&sbuf[0][0]) + NBINS;
    for (int i = tid; i < NBINS; i += TPB) s_h[i] = g_z.hist[r][i];
    __syncthreads();

    const unsigned pcr = g_z.pos_cnt[r];
    const unsigned bcr = g_z.big_cnt[r];
    const double   bsa = g_z.big_suma[r];
    unsigned k = 2u * pcr; if (k > (unsigned)(N - 1)) k = (unsigned)(N - 1);
    const unsigned keff = (k < bcr) ? k : bcr;

    double negr = 0.0;                          // meaningful in tid 0
    if (keff > 0) {
        if (tid < 32) warp_select(s_h, NBINS, keff, &s_b, &s_c);
        __syncthreads();
        const int b1 = s_b; const unsigned cab = s_c;
        double unsel = 0.0;                     // a-sum over unselected bigs
        for (int b = tid; b < b1; b += TPB)
            unsel += (double)s_h[b] * (double)bin_center(b);
        unsel = block_reduce_double(unsel);
        if (tid == 0) {
            unsigned part_unsel = s_h[b1] - (keff - cab);
            unsel += (double)part_unsel * (double)bin_center(b1);
            negr = bsa - unsel - 0.5 * (double)keff;
        }
    }

    // rare fallback: k exceeds big count -> top (k-bc) among below-cut negs
    if (bcr < k) {
        __syncthreads();
        for (int i = tid; i < NBINS; i += TPB) { s_h[i] = 0u; s_f[i] = 0.f; }
        __syncthreads();
        const size_t rb = (size_t)r * N;
        for (int i = tid; i < N; i += TPB) {
            float p = yp[rb + i], t = yt[rb + i];
            if (t == 0.f) {
                float a = fabsf(p);
                if (a < CUTF) {
                    unsigned bin = __float_as_uint(a) >> 19;
                    if (bin > (unsigned)(NBINS - 1)) bin = NBINS - 1;
                    atomicAdd(&s_h[bin], 1u);
                    atomicAdd(&s_f[bin], fsl1(a));
                }
            }
        }
        __syncthreads();
        double dt = 0.0;
        for (int i = tid; i < NBINS; i += TPB) dt += (double)s_h[i];
        dt = block_reduce_double(dt);
        if (tid == 0) s_c = (unsigned)(dt + 0.5);
        __syncthreads();
        unsigned tot = s_c;
        __syncthreads();
        unsigned kc = k - bcr; if (kc > tot) kc = tot;
        if (kc > 0) {
            if (tid < 32) warp_select(s_h, NBINS, kc, &s_b, &s_c);
            __syncthreads();
            const int b1 = s_b; const unsigned cab = s_c;
            double ext = 0.0;
            for (int b = b1 + 1 + tid; b < NBINS; b += TPB) ext += (double)s_f[b];
            ext = block_reduce_double(ext);
            if (tid == 0) {
                unsigned part = kc - cab;
                if (s_h[b1]) ext += (double)part * ((double)s_f[b1] / (double)s_h[b1]);
                negr += ext;
            }
        }
    }

    if (tid == 0) {
        atomicAdd(&g_z.ns, negr);
        atomicAdd(&g_z.nc, (double)k);
        __threadfence();
        s_fin2 = (atomicAdd(&g_z.ticket2, 1u) == (unsigned)(B - 1)) ? 1 : 0;
    }
    __syncthreads();
    if (!s_fin2) return;

    // ================= final scalar (one block total) ========================
    __threadfence();
    double ps  = (tid < B) ? g_z.pos_sum[tid] : 0.0;
    double pcs = (tid < B) ? (double)g_z.pos_cnt[tid] : 0.0;
    ps = block_reduce_double(ps);
    pcs = block_reduce_double(pcs);
    if (tid == 0) {
        double NS = g_z.ns, NC = g_z.nc;
        double pos_loss = (pcs > 0.0) ? ps / pcs : 0.0;
        double neg_loss = (NC > 0.0) ? NS / NC : 0.0;
        out[0] = (float)(2.0 * pos_loss + neg_loss);
    }
}

// ---------------- launch ------------------------------------------------------
extern "C" void kernel_launch(void* const* d_in, const int* in_sizes, int n_in,
                              void* d_out, int out_size) {
    const float* yp = (const float*)d_in[0];
    const float* yt = (const float*)d_in[1];
    float* out = (float*)d_out;

    void* zp = nullptr;
    cudaGetSymbolAddress(&zp, g_z);
    cudaMemsetAsync(zp, 0, sizeof(Zeroed));

    fused<<<dim3(BPR, B), TPB>>>(yp, yt, out);
}